// round 3
// baseline (speedup 1.0000x reference)
#include <cuda_runtime.h>

#define D 128
#define NMAX 50000
#define EMAX 1000000
#define SCAN_T 1024

// Scratch (static device globals: allocation-free, graph-capture safe)
__device__ float g_bufA[(size_t)NMAX * D];   // GEMM outputs (pre-scaled by dinv[src])
__device__ float g_bufB[(size_t)NMAX * D];   // gather accumulators / GEMM2 input
__device__ float g_dinv[NMAX];               // deg^-1/2
__device__ int   g_deg[NMAX];                // integer in-degree
__device__ int   g_off[NMAX];                // CSR row offsets (by dst)
__device__ int   g_cur[NMAX];                // fill cursors
__device__ int   g_csr[EMAX];                // CSR column (src) indices
__device__ int   g_is32;                     // edge dtype flag (1 = int32, 0 = int64)

// ---------------------------------------------------------------------------
// Edge dtype detection: reinterpret the first words as int64. If the data is
// really int32 node ids (< NMAX), the packed high half is nonzero for almost
// every word, so any value >= n_nodes proves int32.
// ---------------------------------------------------------------------------
__global__ void detect_kernel(const unsigned long long* __restrict__ e, int nwords, int nnodes) {
    __shared__ int flag;
    if (threadIdx.x == 0) flag = 0;
    __syncthreads();
    int bad = 0;
    for (int i = threadIdx.x; i < nwords; i += blockDim.x)
        if (e[i] >= (unsigned long long)nnodes) bad = 1;
    if (bad) flag = 1;
    __syncthreads();
    if (threadIdx.x == 0) g_is32 = flag;
}

__global__ void zero_deg_kernel(int n) {
    int i = blockIdx.x * blockDim.x + threadIdx.x;
    if (i < n) g_deg[i] = 0;
}

__global__ void deg_kernel(const void* __restrict__ edges, int E) {
    int e = blockIdx.x * blockDim.x + threadIdx.x;
    if (e >= E) return;
    int dst;
    if (g_is32) dst = ((const int*)edges)[E + e];
    else        dst = (int)((const long long*)edges)[E + e];
    atomicAdd(&g_deg[dst], 1);
}

// Single-block exclusive scan over degrees; also derives dinv = deg^-1/2.
__global__ void scan_kernel(int n) {
    __shared__ int part[SCAN_T];
    int t = threadIdx.x;
    int chunk = (n + SCAN_T - 1) / SCAN_T;
    int b = t * chunk, e = min(b + chunk, n);
    int s = 0;
    for (int i = b; i < e; i++) s += g_deg[i];
    part[t] = s;
    __syncthreads();
    for (int d = 1; d < SCAN_T; d <<= 1) {
        int v = part[t];
        int add = (t >= d) ? part[t - d] : 0;
        __syncthreads();
        part[t] = v + add;
        __syncthreads();
    }
    int off = (t > 0) ? part[t - 1] : 0;
    for (int i = b; i < e; i++) {
        g_off[i] = off;
        g_cur[i] = off;
        int dg = g_deg[i];
        g_dinv[i] = (dg > 0) ? rsqrtf((float)dg) : 0.f;
        off += dg;
    }
}

__global__ void fill_kernel(const void* __restrict__ edges, int E) {
    int e = blockIdx.x * blockDim.x + threadIdx.x;
    if (e >= E) return;
    int src, dst;
    if (g_is32) {
        const int* p = (const int*)edges;
        src = p[e]; dst = p[E + e];
    } else {
        const long long* p = (const long long*)edges;
        src = (int)p[e]; dst = (int)p[E + e];
    }
    int pos = atomicAdd(&g_cur[dst], 1);
    g_csr[pos] = src;
}

// ---------------------------------------------------------------------------
// SGEMM: out[row][n] = dinv[row] * sum_k A[row][k] * W[k][n]
//   LAYER 1: A = x (input), W = w1 [128,128]
//   LAYER 2: A[row][k] = relu(dinv[row]*g_bufB[row][k] + b1[k]),
//            W[:, 0:64] = w_mu, W[:, 64:128] = w_ls  (both [128,64])
// Output always g_bufA. BM=128, BN=128, BK=128, 256 threads, 8x8 reg tiles.
// ---------------------------------------------------------------------------
template<int LAYER>
__global__ void gemm_kernel(const float* __restrict__ Xin,
                            const float* __restrict__ Wa,
                            const float* __restrict__ Wb,
                            const float* __restrict__ bias1,
                            int N)
{
    extern __shared__ float sm[];
    float* Ws = sm;             // [k][n] 128x128
    float* Xs = sm + D * D;     // [k][m] 128x128 (transposed tile)
    const int t = threadIdx.x;
    const int row0 = blockIdx.x * 128;
    const float* X = (LAYER == 1) ? Xin : g_bufB;

#pragma unroll
    for (int i = 0; i < 16; i++) {
        int idx = t + 256 * i;           // float4 index over [128][32]
        int k = idx >> 5, n4 = idx & 31;
        float4 w;
        if (LAYER == 1) {
            w = ((const float4*)Wa)[idx];
        } else {
            if (n4 < 16) w = *(const float4*)(Wa + k * 64 + n4 * 4);
            else         w = *(const float4*)(Wb + k * 64 + (n4 - 16) * 4);
        }
        ((float4*)Ws)[idx] = w;
    }

#pragma unroll
    for (int i = 0; i < 16; i++) {
        int idx = t + 256 * i;           // m fastest -> conflict-free smem stores
        int m = idx & 127, k4 = idx >> 7;
        int row = row0 + m;
        float4 v = make_float4(0.f, 0.f, 0.f, 0.f);
        if (row < N) {
            v = *(const float4*)(X + (size_t)row * D + k4 * 4);
            if (LAYER == 2) {
                float di = g_dinv[row];
                v.x = fmaxf(fmaf(di, v.x, __ldg(bias1 + k4 * 4 + 0)), 0.f);
                v.y = fmaxf(fmaf(di, v.y, __ldg(bias1 + k4 * 4 + 1)), 0.f);
                v.z = fmaxf(fmaf(di, v.z, __ldg(bias1 + k4 * 4 + 2)), 0.f);
                v.w = fmaxf(fmaf(di, v.w, __ldg(bias1 + k4 * 4 + 3)), 0.f);
            }
        }
        Xs[(k4 * 4 + 0) * D + m] = v.x;
        Xs[(k4 * 4 + 1) * D + m] = v.y;
        Xs[(k4 * 4 + 2) * D + m] = v.z;
        Xs[(k4 * 4 + 3) * D + m] = v.w;
    }
    __syncthreads();

    const int tx = t & 15, ty = t >> 4;
    float acc[8][8];
#pragma unroll
    for (int i = 0; i < 8; i++)
#pragma unroll
        for (int j = 0; j < 8; j++) acc[i][j] = 0.f;

#pragma unroll 8
    for (int k = 0; k < D; k++) {
        float a[8], b[8];
        *(float4*)(a)     = *(const float4*)(Xs + k * D + ty * 8);
        *(float4*)(a + 4) = *(const float4*)(Xs + k * D + ty * 8 + 4);
        *(float4*)(b)     = *(const float4*)(Ws + k * D + tx * 8);
        *(float4*)(b + 4) = *(const float4*)(Ws + k * D + tx * 8 + 4);
#pragma unroll
        for (int i = 0; i < 8; i++)
#pragma unroll
            for (int j = 0; j < 8; j++)
                acc[i][j] = fmaf(a[i], b[j], acc[i][j]);
    }

#pragma unroll
    for (int i = 0; i < 8; i++) {
        int row = row0 + ty * 8 + i;
        if (row >= N) continue;
        float di = g_dinv[row];
        float4 o0, o1;
        o0.x = acc[i][0] * di; o0.y = acc[i][1] * di;
        o0.z = acc[i][2] * di; o0.w = acc[i][3] * di;
        o1.x = acc[i][4] * di; o1.y = acc[i][5] * di;
        o1.z = acc[i][6] * di; o1.w = acc[i][7] * di;
        *(float4*)(g_bufA + (size_t)row * D + tx * 8)     = o0;
        *(float4*)(g_bufA + (size_t)row * D + tx * 8 + 4) = o1;
    }
}

// ---------------------------------------------------------------------------
// Gather-reduce: one warp per destination node. Lane l owns columns [4l,4l+4).
// bufB[dst] = sum over CSR neighbors of bufA[src] (rows carry dinv[src]).
// No atomics; fully coalesced writes. Unrolled x4 for memory-level parallelism.
// ---------------------------------------------------------------------------
__global__ void gather_kernel(int N) {
    int gid = blockIdx.x * blockDim.x + threadIdx.x;
    int node = gid >> 5;
    if (node >= N) return;
    int lane = gid & 31;
    int beg = g_off[node];
    int cnt = g_deg[node];
    const float* base = g_bufA + (size_t)lane * 4;

    float4 acc = make_float4(0.f, 0.f, 0.f, 0.f);
    int k = 0;
    for (; k + 4 <= cnt; k += 4) {
        int s0 = g_csr[beg + k + 0];
        int s1 = g_csr[beg + k + 1];
        int s2 = g_csr[beg + k + 2];
        int s3 = g_csr[beg + k + 3];
        float4 v0 = *(const float4*)(base + (size_t)s0 * D);
        float4 v1 = *(const float4*)(base + (size_t)s1 * D);
        float4 v2 = *(const float4*)(base + (size_t)s2 * D);
        float4 v3 = *(const float4*)(base + (size_t)s3 * D);
        acc.x += v0.x + v1.x + v2.x + v3.x;
        acc.y += v0.y + v1.y + v2.y + v3.y;
        acc.z += v0.z + v1.z + v2.z + v3.z;
        acc.w += v0.w + v1.w + v2.w + v3.w;
    }
    for (; k < cnt; k++) {
        int s = g_csr[beg + k];
        float4 v = *(const float4*)(base + (size_t)s * D);
        acc.x += v.x; acc.y += v.y; acc.z += v.z; acc.w += v.w;
    }
    *(float4*)(g_bufB + (size_t)node * D + lane * 4) = acc;
}

// ---------------------------------------------------------------------------
// Final: mu = dinv[i]*agg2[:, :64] + b_mu ; logstd = dinv[i]*agg2[:, 64:] + b_ls
// Output layout: [mu (N x 64), logstd (N x 64)] concatenated.
// ---------------------------------------------------------------------------
__global__ void final_kernel(const float* __restrict__ bmu,
                             const float* __restrict__ bls,
                             float* __restrict__ out, int N)
{
    int gid = blockIdx.x * blockDim.x + threadIdx.x;
    if (gid >= N * 16) return;
    int i = gid >> 4, c4 = gid & 15;
    float di = g_dinv[i];
    float4 m  = *(const float4*)(g_bufB + (size_t)i * D + c4 * 4);
    float4 l  = *(const float4*)(g_bufB + (size_t)i * D + 64 + c4 * 4);
    float4 bm = *(const float4*)(bmu + c4 * 4);
    float4 bl = *(const float4*)(bls + c4 * 4);
    float4 om = make_float4(fmaf(di, m.x, bm.x), fmaf(di, m.y, bm.y),
                            fmaf(di, m.z, bm.z), fmaf(di, m.w, bm.w));
    float4 ol = make_float4(fmaf(di, l.x, bl.x), fmaf(di, l.y, bl.y),
                            fmaf(di, l.z, bl.z), fmaf(di, l.w, bl.w));
    *(float4*)(out + (size_t)i * 64 + c4 * 4) = om;
    *(float4*)(out + (size_t)N * 64 + (size_t)i * 64 + c4 * 4) = ol;
}

// ---------------------------------------------------------------------------
extern "C" void kernel_launch(void* const* d_in, const int* in_sizes, int n_in,
                              void* d_out, int out_size)
{
    const float* x   = (const float*)d_in[0];
    const void*  edg = d_in[1];
    const float* w1  = (const float*)d_in[2];
    const float* b1  = (const float*)d_in[3];
    const float* wmu = (const float*)d_in[4];
    const float* bmu = (const float*)d_in[5];
    const float* wls = (const float*)d_in[6];
    const float* bls = (const float*)d_in[7];
    float* out = (float*)d_out;

    const int N = in_sizes[0] / D;
    const int E = in_sizes[1] / 2;

    const size_t smem = 2 * (size_t)D * D * sizeof(float);  // 128 KB
    cudaFuncSetAttribute(gemm_kernel<1>, cudaFuncAttributeMaxDynamicSharedMemorySize, (int)smem);
    cudaFuncSetAttribute(gemm_kernel<2>, cudaFuncAttributeMaxDynamicSharedMemorySize, (int)smem);

    const int nw = E < 1024 ? E : 1024;
    detect_kernel<<<1, 256>>>((const unsigned long long*)edg, nw, N);

    // CSR build (by destination) + normalization
    zero_deg_kernel<<<(N + 255) / 256, 256>>>(N);
    deg_kernel<<<(E + 255) / 256, 256>>>(edg, E);
    scan_kernel<<<1, SCAN_T>>>(N);
    fill_kernel<<<(E + 255) / 256, 256>>>(edg, E);

    const int gemm_blocks = (N + 127) / 128;
    const int gath_blocks = (int)(((long long)N * 32 + 255) / 256);

    // Layer 1: H1s = dinv .* (x @ W1) ; agg1 = gather(H1s)
    gemm_kernel<1><<<gemm_blocks, 256, smem>>>(x, w1, nullptr, nullptr, N);
    gather_kernel<<<gath_blocks, 256>>>(N);

    // Layer 2: h = relu(dinv .* agg1 + b1); H2s = dinv .* (h @ [w_mu|w_ls])
    gemm_kernel<2><<<gemm_blocks, 256, smem>>>(nullptr, wmu, wls, b1, N);
    gather_kernel<<<gath_blocks, 256>>>(N);

    // Epilogue: scale by dinv[dst], add biases, split mu/logstd
    final_kernel<<<(N * 16 + 255) / 256, 256>>>(bmu, bls, out, N);
}

// round 4
// speedup vs baseline: 1.0039x; 1.0039x over previous
#include <cuda_runtime.h>

#define D 128
#define NMAX 50000
#define EMAX 1000000
#define SCAN_T 1024

// Scratch (static device globals: allocation-free, graph-capture safe)
__device__ float g_bufA[(size_t)NMAX * D];   // GEMM outputs (pre-scaled by dinv[src])
__device__ float g_bufB[(size_t)NMAX * D];   // gather accumulators / GEMM2 input
__device__ float g_dinv[NMAX];               // deg^-1/2
__device__ int   g_deg[NMAX];                // integer in-degree
__device__ int   g_off[NMAX];                // CSR row offsets (by dst)
__device__ int   g_cur[NMAX];                // fill cursors
__device__ int   g_csr[EMAX];                // CSR column (src) indices
__device__ int   g_is32;                     // edge dtype flag (1 = int32, 0 = int64)

// ---------------------------------------------------------------------------
// Edge dtype detection: reinterpret the first words as int64. If the data is
// really int32 node ids (< NMAX), the packed high half is nonzero for almost
// every word, so any value >= n_nodes proves int32.
// ---------------------------------------------------------------------------
__global__ void detect_kernel(const unsigned long long* __restrict__ e, int nwords, int nnodes) {
    __shared__ int flag;
    if (threadIdx.x == 0) flag = 0;
    __syncthreads();
    int bad = 0;
    for (int i = threadIdx.x; i < nwords; i += blockDim.x)
        if (e[i] >= (unsigned long long)nnodes) bad = 1;
    if (bad) flag = 1;
    __syncthreads();
    if (threadIdx.x == 0) g_is32 = flag;
}

__global__ void zero_deg_kernel(int n) {
    int i = blockIdx.x * blockDim.x + threadIdx.x;
    if (i < n) g_deg[i] = 0;
}

__global__ void deg_kernel(const void* __restrict__ edges, int E) {
    int e = blockIdx.x * blockDim.x + threadIdx.x;
    if (e >= E) return;
    int dst;
    if (g_is32) dst = ((const int*)edges)[E + e];
    else        dst = (int)((const long long*)edges)[E + e];
    atomicAdd(&g_deg[dst], 1);
}

// Single-block exclusive scan over degrees; also derives dinv = deg^-1/2.
__global__ void scan_kernel(int n) {
    __shared__ int part[SCAN_T];
    int t = threadIdx.x;
    int chunk = (n + SCAN_T - 1) / SCAN_T;
    int b = t * chunk, e = min(b + chunk, n);
    int s = 0;
    for (int i = b; i < e; i++) s += g_deg[i];
    part[t] = s;
    __syncthreads();
    for (int d = 1; d < SCAN_T; d <<= 1) {
        int v = part[t];
        int add = (t >= d) ? part[t - d] : 0;
        __syncthreads();
        part[t] = v + add;
        __syncthreads();
    }
    int off = (t > 0) ? part[t - 1] : 0;
    for (int i = b; i < e; i++) {
        g_off[i] = off;
        g_cur[i] = off;
        int dg = g_deg[i];
        g_dinv[i] = (dg > 0) ? rsqrtf((float)dg) : 0.f;
        off += dg;
    }
}

__global__ void fill_kernel(const void* __restrict__ edges, int E) {
    int e = blockIdx.x * blockDim.x + threadIdx.x;
    if (e >= E) return;
    int src, dst;
    if (g_is32) {
        const int* p = (const int*)edges;
        src = p[e]; dst = p[E + e];
    } else {
        const long long* p = (const long long*)edges;
        src = (int)p[e]; dst = (int)p[E + e];
    }
    int pos = atomicAdd(&g_cur[dst], 1);
    g_csr[pos] = src;
}

// ---------------------------------------------------------------------------
// SGEMM: out[row][n] = dinv[row] * sum_k A[row][k] * W[k][n]
//   LAYER 1: A = x (input), W = w1 [128,128]
//   LAYER 2: A[row][k] = relu(dinv[row]*g_bufB[row][k] + b1[k]),
//            W[:, 0:64] = w_mu, W[:, 64:128] = w_ls  (both [128,64])
// Output always g_bufA. BM=128, BN=128, BK=128, 256 threads, 8x8 reg tiles.
// ---------------------------------------------------------------------------
template<int LAYER>
__global__ void gemm_kernel(const float* __restrict__ Xin,
                            const float* __restrict__ Wa,
                            const float* __restrict__ Wb,
                            const float* __restrict__ bias1,
                            int N)
{
    extern __shared__ float sm[];
    float* Ws = sm;             // [k][n] 128x128
    float* Xs = sm + D * D;     // [k][m] 128x128 (transposed tile)
    const int t = threadIdx.x;
    const int row0 = blockIdx.x * 128;
    const float* X = (LAYER == 1) ? Xin : g_bufB;

#pragma unroll
    for (int i = 0; i < 16; i++) {
        int idx = t + 256 * i;           // float4 index over [128][32]
        int k = idx >> 5, n4 = idx & 31;
        float4 w;
        if (LAYER == 1) {
            w = ((const float4*)Wa)[idx];
        } else {
            if (n4 < 16) w = *(const float4*)(Wa + k * 64 + n4 * 4);
            else         w = *(const float4*)(Wb + k * 64 + (n4 - 16) * 4);
        }
        ((float4*)Ws)[idx] = w;
    }

#pragma unroll
    for (int i = 0; i < 16; i++) {
        int idx = t + 256 * i;           // m fastest -> conflict-free smem stores
        int m = idx & 127, k4 = idx >> 7;
        int row = row0 + m;
        float4 v = make_float4(0.f, 0.f, 0.f, 0.f);
        if (row < N) {
            v = *(const float4*)(X + (size_t)row * D + k4 * 4);
            if (LAYER == 2) {
                float di = g_dinv[row];
                v.x = fmaxf(fmaf(di, v.x, __ldg(bias1 + k4 * 4 + 0)), 0.f);
                v.y = fmaxf(fmaf(di, v.y, __ldg(bias1 + k4 * 4 + 1)), 0.f);
                v.z = fmaxf(fmaf(di, v.z, __ldg(bias1 + k4 * 4 + 2)), 0.f);
                v.w = fmaxf(fmaf(di, v.w, __ldg(bias1 + k4 * 4 + 3)), 0.f);
            }
        }
        Xs[(k4 * 4 + 0) * D + m] = v.x;
        Xs[(k4 * 4 + 1) * D + m] = v.y;
        Xs[(k4 * 4 + 2) * D + m] = v.z;
        Xs[(k4 * 4 + 3) * D + m] = v.w;
    }
    __syncthreads();

    const int tx = t & 15, ty = t >> 4;
    float acc[8][8];
#pragma unroll
    for (int i = 0; i < 8; i++)
#pragma unroll
        for (int j = 0; j < 8; j++) acc[i][j] = 0.f;

#pragma unroll 8
    for (int k = 0; k < D; k++) {
        float a[8], b[8];
        *(float4*)(a)     = *(const float4*)(Xs + k * D + ty * 8);
        *(float4*)(a + 4) = *(const float4*)(Xs + k * D + ty * 8 + 4);
        *(float4*)(b)     = *(const float4*)(Ws + k * D + tx * 8);
        *(float4*)(b + 4) = *(const float4*)(Ws + k * D + tx * 8 + 4);
#pragma unroll
        for (int i = 0; i < 8; i++)
#pragma unroll
            for (int j = 0; j < 8; j++)
                acc[i][j] = fmaf(a[i], b[j], acc[i][j]);
    }

#pragma unroll
    for (int i = 0; i < 8; i++) {
        int row = row0 + ty * 8 + i;
        if (row >= N) continue;
        float di = g_dinv[row];
        float4 o0, o1;
        o0.x = acc[i][0] * di; o0.y = acc[i][1] * di;
        o0.z = acc[i][2] * di; o0.w = acc[i][3] * di;
        o1.x = acc[i][4] * di; o1.y = acc[i][5] * di;
        o1.z = acc[i][6] * di; o1.w = acc[i][7] * di;
        *(float4*)(g_bufA + (size_t)row * D + tx * 8)     = o0;
        *(float4*)(g_bufA + (size_t)row * D + tx * 8 + 4) = o1;
    }
}

// ---------------------------------------------------------------------------
// Gather-reduce: one warp per destination node. Lane l owns columns [4l,4l+4).
// bufB[dst] = sum over CSR neighbors of bufA[src] (rows carry dinv[src]).
// No atomics; fully coalesced writes. Unrolled x4 for memory-level parallelism.
// ---------------------------------------------------------------------------
__global__ void gather_kernel(int N) {
    int gid = blockIdx.x * blockDim.x + threadIdx.x;
    int node = gid >> 5;
    if (node >= N) return;
    int lane = gid & 31;
    int beg = g_off[node];
    int cnt = g_deg[node];
    const float* base = g_bufA + (size_t)lane * 4;

    float4 acc = make_float4(0.f, 0.f, 0.f, 0.f);
    int k = 0;
    for (; k + 4 <= cnt; k += 4) {
        int s0 = g_csr[beg + k + 0];
        int s1 = g_csr[beg + k + 1];
        int s2 = g_csr[beg + k + 2];
        int s3 = g_csr[beg + k + 3];
        float4 v0 = *(const float4*)(base + (size_t)s0 * D);
        float4 v1 = *(const float4*)(base + (size_t)s1 * D);
        float4 v2 = *(const float4*)(base + (size_t)s2 * D);
        float4 v3 = *(const float4*)(base + (size_t)s3 * D);
        acc.x += v0.x + v1.x + v2.x + v3.x;
        acc.y += v0.y + v1.y + v2.y + v3.y;
        acc.z += v0.z + v1.z + v2.z + v3.z;
        acc.w += v0.w + v1.w + v2.w + v3.w;
    }
    for (; k < cnt; k++) {
        int s = g_csr[beg + k];
        float4 v = *(const float4*)(base + (size_t)s * D);
        acc.x += v.x; acc.y += v.y; acc.z += v.z; acc.w += v.w;
    }
    *(float4*)(g_bufB + (size_t)node * D + lane * 4) = acc;
}

// ---------------------------------------------------------------------------
// Final: mu = dinv[i]*agg2[:, :64] + b_mu ; logstd = dinv[i]*agg2[:, 64:] + b_ls
// Output layout: [mu (N x 64), logstd (N x 64)] concatenated.
// ---------------------------------------------------------------------------
__global__ void final_kernel(const float* __restrict__ bmu,
                             const float* __restrict__ bls,
                             float* __restrict__ out, int N)
{
    int gid = blockIdx.x * blockDim.x + threadIdx.x;
    if (gid >= N * 16) return;
    int i = gid >> 4, c4 = gid & 15;
    float di = g_dinv[i];
    float4 m  = *(const float4*)(g_bufB + (size_t)i * D + c4 * 4);
    float4 l  = *(const float4*)(g_bufB + (size_t)i * D + 64 + c4 * 4);
    float4 bm = *(const float4*)(bmu + c4 * 4);
    float4 bl = *(const float4*)(bls + c4 * 4);
    float4 om = make_float4(fmaf(di, m.x, bm.x), fmaf(di, m.y, bm.y),
                            fmaf(di, m.z, bm.z), fmaf(di, m.w, bm.w));
    float4 ol = make_float4(fmaf(di, l.x, bl.x), fmaf(di, l.y, bl.y),
                            fmaf(di, l.z, bl.z), fmaf(di, l.w, bl.w));
    *(float4*)(out + (size_t)i * 64 + c4 * 4) = om;
    *(float4*)(out + (size_t)N * 64 + (size_t)i * 64 + c4 * 4) = ol;
}

// ---------------------------------------------------------------------------
extern "C" void kernel_launch(void* const* d_in, const int* in_sizes, int n_in,
                              void* d_out, int out_size)
{
    const float* x   = (const float*)d_in[0];
    const void*  edg = d_in[1];
    const float* w1  = (const float*)d_in[2];
    const float* b1  = (const float*)d_in[3];
    const float* wmu = (const float*)d_in[4];
    const float* bmu = (const float*)d_in[5];
    const float* wls = (const float*)d_in[6];
    const float* bls = (const float*)d_in[7];
    float* out = (float*)d_out;

    const int N = in_sizes[0] / D;
    const int E = in_sizes[1] / 2;

    const size_t smem = 2 * (size_t)D * D * sizeof(float);  // 128 KB
    cudaFuncSetAttribute(gemm_kernel<1>, cudaFuncAttributeMaxDynamicSharedMemorySize, (int)smem);
    cudaFuncSetAttribute(gemm_kernel<2>, cudaFuncAttributeMaxDynamicSharedMemorySize, (int)smem);

    const int nw = E < 1024 ? E : 1024;
    detect_kernel<<<1, 256>>>((const unsigned long long*)edg, nw, N);

    // CSR build (by destination) + normalization
    zero_deg_kernel<<<(N + 255) / 256, 256>>>(N);
    deg_kernel<<<(E + 255) / 256, 256>>>(edg, E);
    scan_kernel<<<1, SCAN_T>>>(N);
    fill_kernel<<<(E + 255) / 256, 256>>>(edg, E);

    const int gemm_blocks = (N + 127) / 128;
    const int gath_blocks = (int)(((long long)N * 32 + 255) / 256);

    // Layer 1: H1s = dinv .* (x @ W1) ; agg1 = gather(H1s)
    gemm_kernel<1><<<gemm_blocks, 256, smem>>>(x, w1, nullptr, nullptr, N);
    gather_kernel<<<gath_blocks, 256>>>(N);

    // Layer 2: h = relu(dinv .* agg1 + b1); H2s = dinv .* (h @ [w_mu|w_ls])
    gemm_kernel<2><<<gemm_blocks, 256, smem>>>(nullptr, wmu, wls, b1, N);
    gather_kernel<<<gath_blocks, 256>>>(N);

    // Epilogue: scale by dinv[dst], add biases, split mu/logstd
    final_kernel<<<(N * 16 + 255) / 256, 256>>>(bmu, bls, out, N);
}